// round 1
// baseline (speedup 1.0000x reference)
#include <cuda_runtime.h>
#include <cuda_bf16.h>

#define B_  8
#define Q_  256
#define K_  1024
#define D_  256
#define H_  128
#define DV_ 128

#define TQ   8
#define TK   128
#define KPAD 132

// scratch for projected q/k
__device__ float g_q[B_ * Q_ * H_];
__device__ float g_k[B_ * K_ * H_];

__device__ __forceinline__ float fast_tanh(float x) {
    float y;
    asm("tanh.approx.f32 %0, %1;" : "=f"(y) : "f"(x));
    return y;
}

// ---------------------------------------------------------------------------
// Kernel 1: fused projections  q = queries @ W_q,  k = keys @ W_k
// One block = 16 rows x 128 h-cols. 128 threads, thread = one h column.
// ---------------------------------------------------------------------------
__global__ __launch_bounds__(128) void proj_kernel(
    const float* __restrict__ queries, const float* __restrict__ keys,
    const float* __restrict__ Wq, const float* __restrict__ Wk)
{
    __shared__ float s_in[16 * D_];
    int rb = blockIdx.x * 16;
    bool isQ = rb < B_ * Q_;
    const float* src = isQ ? (queries + rb * D_) : (keys + (rb - B_ * Q_) * D_);
    const float* W   = isQ ? Wq : Wk;
    float* dst       = isQ ? (g_q + rb * H_) : (g_k + (rb - B_ * Q_) * H_);

    int tid = threadIdx.x;
    const float4* s4 = (const float4*)src;
    float4* d4 = (float4*)s_in;
    #pragma unroll
    for (int i = 0; i < 8; i++) d4[tid + 128 * i] = s4[tid + 128 * i];
    __syncthreads();

    float acc[16];
    #pragma unroll
    for (int r = 0; r < 16; r++) acc[r] = 0.f;

    #pragma unroll 4
    for (int d = 0; d < D_; d += 4) {
        float w0 = W[(d + 0) * H_ + tid];
        float w1 = W[(d + 1) * H_ + tid];
        float w2 = W[(d + 2) * H_ + tid];
        float w3 = W[(d + 3) * H_ + tid];
        #pragma unroll
        for (int r = 0; r < 16; r++) {
            float4 a = *(const float4*)&s_in[r * D_ + d];
            acc[r] += a.x * w0 + a.y * w1 + a.z * w2 + a.w * w3;
        }
    }
    #pragma unroll
    for (int r = 0; r < 16; r++) dst[r * H_ + tid] = acc[r];
}

// ---------------------------------------------------------------------------
// Kernel 2: scores (tanh) + masked softmax + attn @ values
// grid = (Q_/TQ, B_), 256 threads. Block handles 8 q-rows of one batch.
// ---------------------------------------------------------------------------
#define SMEM_FLOATS (TK * KPAD + TQ * KPAD + H_ + TQ * K_)
#define SMEM_BYTES  (SMEM_FLOATS * 4)

__global__ __launch_bounds__(256) void attn_kernel(
    const float* __restrict__ values, const int* __restrict__ valid_lens,
    const float* __restrict__ w_v, float* __restrict__ out)
{
    extern __shared__ float sm[];
    float* ks = sm;                     // TK * KPAD
    float* qs = ks + TK * KPAD;         // TQ * KPAD
    float* wv = qs + TQ * KPAD;         // H_
    float* sc = wv + H_;                // TQ * K_   (scores -> attn)

    int b  = blockIdx.y;
    int q0 = blockIdx.x * TQ;
    int tid = threadIdx.x;
    int vlen = valid_lens[b];

    // load q rows (padded) and w_v
    for (int i = tid; i < TQ * H_; i += 256) {
        int r = i >> 7, h = i & 127;
        qs[r * KPAD + h] = g_q[(b * Q_ + q0 + r) * H_ + h];
    }
    if (tid < H_) wv[tid] = w_v[tid];

    int qg = tid >> 6;   // 0..3 -> 2 q rows each
    int kg = tid & 63;   // 0..63 -> k rows kg and kg+64 of the tile
    const float4* q0p = (const float4*)(qs + (qg * 2    ) * KPAD);
    const float4* q1p = (const float4*)(qs + (qg * 2 + 1) * KPAD);
    const float4* k0p = (const float4*)(ks + kg * KPAD);
    const float4* k1p = (const float4*)(ks + (kg + 64) * KPAD);
    const float4* wvp = (const float4*)wv;

    for (int kt = 0; kt < K_; kt += TK) {
        __syncthreads();
        // cooperative load of k tile (float4, padded stride)
        const float4* srck = (const float4*)(g_k + (b * K_ + kt) * H_);
        for (int i = tid; i < TK * 32; i += 256) {
            int r = i >> 5, c = i & 31;
            *(float4*)(ks + r * KPAD + c * 4) = srck[i];
        }
        __syncthreads();

        float s00 = 0.f, s01 = 0.f, s10 = 0.f, s11 = 0.f;
        #pragma unroll 8
        for (int h4 = 0; h4 < 32; h4++) {
            float4 a0 = q0p[h4], a1 = q1p[h4];
            float4 c0 = k0p[h4], c1 = k1p[h4];
            float4 w  = wvp[h4];
            s00 += w.x * fast_tanh(a0.x + c0.x);
            s00 += w.y * fast_tanh(a0.y + c0.y);
            s00 += w.z * fast_tanh(a0.z + c0.z);
            s00 += w.w * fast_tanh(a0.w + c0.w);
            s01 += w.x * fast_tanh(a0.x + c1.x);
            s01 += w.y * fast_tanh(a0.y + c1.y);
            s01 += w.z * fast_tanh(a0.z + c1.z);
            s01 += w.w * fast_tanh(a0.w + c1.w);
            s10 += w.x * fast_tanh(a1.x + c0.x);
            s10 += w.y * fast_tanh(a1.y + c0.y);
            s10 += w.z * fast_tanh(a1.z + c0.z);
            s10 += w.w * fast_tanh(a1.w + c0.w);
            s11 += w.x * fast_tanh(a1.x + c1.x);
            s11 += w.y * fast_tanh(a1.y + c1.y);
            s11 += w.z * fast_tanh(a1.z + c1.z);
            s11 += w.w * fast_tanh(a1.w + c1.w);
        }
        sc[(qg * 2    ) * K_ + kt + kg     ] = s00;
        sc[(qg * 2    ) * K_ + kt + kg + 64] = s01;
        sc[(qg * 2 + 1) * K_ + kt + kg     ] = s10;
        sc[(qg * 2 + 1) * K_ + kt + kg + 64] = s11;
    }
    __syncthreads();

    // masked softmax: warp w handles q-row w (8 warps, 8 rows)
    {
        int wid = tid >> 5, lane = tid & 31;
        float* row = sc + wid * K_;
        float v[32];
        float m = -3e38f;
        #pragma unroll
        for (int j = 0; j < 32; j++) {
            int k = lane + 32 * j;
            float s = (k < vlen) ? row[k] : -1e6f;
            v[j] = s;
            m = fmaxf(m, s);
        }
        #pragma unroll
        for (int off = 16; off; off >>= 1)
            m = fmaxf(m, __shfl_xor_sync(0xffffffffu, m, off));
        float sum = 0.f;
        #pragma unroll
        for (int j = 0; j < 32; j++) { v[j] = __expf(v[j] - m); sum += v[j]; }
        #pragma unroll
        for (int off = 16; off; off >>= 1)
            sum += __shfl_xor_sync(0xffffffffu, sum, off);
        float inv = 1.f / sum;
        #pragma unroll
        for (int j = 0; j < 32; j++) row[lane + 32 * j] = v[j] * inv;
    }
    __syncthreads();

    // attn @ values: thread = (v4 = tid&31 float4-col, slice = tid>>5 k-slice)
    {
        int v4 = tid & 31;
        int slice = tid >> 5;
        float4 acc[TQ];
        #pragma unroll
        for (int r = 0; r < TQ; r++) acc[r] = make_float4(0.f, 0.f, 0.f, 0.f);
        const float4* vb = (const float4*)(values + b * K_ * DV_);
        #pragma unroll 2
        for (int k = slice; k < K_; k += 8) {
            float4 vv = vb[k * 32 + v4];
            #pragma unroll
            for (int r = 0; r < TQ; r++) {
                float a = sc[r * K_ + k];
                acc[r].x += a * vv.x; acc[r].y += a * vv.y;
                acc[r].z += a * vv.z; acc[r].w += a * vv.w;
            }
        }
        // cross-slice reduction via smem (reuse ks region: needs 8192 floats)
        float4* red = (float4*)ks;
        #pragma unroll
        for (int r = 0; r < TQ; r++) red[(slice * TQ + r) * 32 + v4] = acc[r];
        __syncthreads();
        int r = tid >> 5, c = tid & 31;
        float4 o = make_float4(0.f, 0.f, 0.f, 0.f);
        #pragma unroll
        for (int s = 0; s < 8; s++) {
            float4 t = red[(s * TQ + r) * 32 + c];
            o.x += t.x; o.y += t.y; o.z += t.z; o.w += t.w;
        }
        ((float4*)(out + (b * Q_ + q0 + r) * DV_))[c] = o;
    }
}

extern "C" void kernel_launch(void* const* d_in, const int* in_sizes, int n_in,
                              void* d_out, int out_size)
{
    const float* queries    = (const float*)d_in[0];
    const float* keys       = (const float*)d_in[1];
    const float* values     = (const float*)d_in[2];
    const int*   valid_lens = (const int*)  d_in[3];
    const float* W_q        = (const float*)d_in[4];
    const float* W_k        = (const float*)d_in[5];
    const float* w_v        = (const float*)d_in[6];
    float* out = (float*)d_out;

    cudaFuncSetAttribute(attn_kernel,
                         cudaFuncAttributeMaxDynamicSharedMemorySize, SMEM_BYTES);

    proj_kernel<<<(B_ * Q_ + B_ * K_) / 16, 128>>>(queries, keys, W_q, W_k);
    attn_kernel<<<dim3(Q_ / TQ, B_), 256, SMEM_BYTES>>>(values, valid_lens, w_v, out);
}

// round 4
// speedup vs baseline: 1.0637x; 1.0637x over previous
#include <cuda_runtime.h>
#include <cuda_fp16.h>
#include <cuda_bf16.h>

#define B_  8
#define Q_  256
#define K_  1024
#define D_  256
#define H_  128
#define DV_ 128

#define TQ   4            // q rows per block
#define TK   128          // k rows per tile (= 64 half2 pairs)
#define RPAD 132          // padded row stride in 4-byte words (33 float4)

// scratch: projected q (half) and k in paired-half2 layout
// g_k2[b][kt][j][h] = (k[b][kt*128+j][h], k[b][kt*128+j+64][h])
__device__ __half  g_qh[B_ * Q_ * H_];
__device__ __half2 g_k2[B_ * (K_ / TK) * (TK / 2) * H_];

__device__ __forceinline__ __half2 tanh_h2(__half2 x) {
    __half2 y;
    asm("tanh.approx.f16x2 %0, %1;"
        : "=r"(*(unsigned int*)&y) : "r"(*(unsigned int*)&x));
    return y;
}

// ---------------------------------------------------------------------------
// Kernel 1: fused projections. Writes q as half, k into paired-half2 layout.
// One block = 16 rows x 128 h. 128 threads, thread = one h column.
// ---------------------------------------------------------------------------
__global__ __launch_bounds__(128) void proj_kernel(
    const float* __restrict__ queries, const float* __restrict__ keys,
    const float* __restrict__ Wq, const float* __restrict__ Wk)
{
    __shared__ float s_in[16 * D_];
    int rb = blockIdx.x * 16;
    bool isQ = rb < B_ * Q_;
    const float* src = isQ ? (queries + rb * D_) : (keys + (rb - B_ * Q_) * D_);
    const float* W   = isQ ? Wq : Wk;

    int tid = threadIdx.x;
    const float4* s4 = (const float4*)src;
    float4* d4 = (float4*)s_in;
    #pragma unroll
    for (int i = 0; i < 8; i++) d4[tid + 128 * i] = s4[tid + 128 * i];
    __syncthreads();

    float acc[16];
    #pragma unroll
    for (int r = 0; r < 16; r++) acc[r] = 0.f;

    #pragma unroll 4
    for (int d = 0; d < D_; d += 4) {
        float w0 = W[(d + 0) * H_ + tid];
        float w1 = W[(d + 1) * H_ + tid];
        float w2 = W[(d + 2) * H_ + tid];
        float w3 = W[(d + 3) * H_ + tid];
        #pragma unroll
        for (int r = 0; r < 16; r++) {
            float4 a = *(const float4*)&s_in[r * D_ + d];
            acc[r] += a.x * w0 + a.y * w1 + a.z * w2 + a.w * w3;
        }
    }

    if (isQ) {
        #pragma unroll
        for (int r = 0; r < 16; r++)
            g_qh[(rb + r) * H_ + tid] = __float2half(acc[r]);
    } else {
        int rk0 = rb - B_ * Q_;
        #pragma unroll
        for (int r = 0; r < 16; r++) {
            int rk = rk0 + r;
            int b   = rk >> 10;
            int rbi = rk & 1023;
            int kt  = rbi >> 7;
            int jj  = rbi & 127;
            int j    = jj & 63;
            int slot = jj >> 6;
            ((__half*)g_k2)[((((b * 8 + kt) * 64 + j) * H_) + tid) * 2 + slot] =
                __float2half(acc[r]);
        }
    }
}

// ---------------------------------------------------------------------------
// Kernel 2: scores (f16x2 tanh) + masked softmax + attn @ values
// grid = (Q_/TQ, B_), 256 threads. Block = 4 q-rows of one batch.
// thread: qg = tid>>6 (one q row), j = tid&63 (k pair j, j+64 of tile)
// ---------------------------------------------------------------------------
#define SMEM_WORDS ((TK/2) * RPAD + TQ * RPAD + RPAD + TQ * K_)
#define SMEM_BYTES (SMEM_WORDS * 4)

__global__ __launch_bounds__(256, 4) void attn_kernel(
    const float* __restrict__ values, const int* __restrict__ valid_lens,
    const float* __restrict__ w_v, float* __restrict__ out)
{
    extern __shared__ float sm[];
    float* ksw = sm;                        // (TK/2) * RPAD words of half2
    float* qsw = ksw + (TK / 2) * RPAD;     // TQ * RPAD words of dup half2
    float* wv  = qsw + TQ * RPAD;           // RPAD fp32
    float* sc  = wv + RPAD;                 // TQ * K_ fp32 scores

    int b   = blockIdx.y;
    int q0  = blockIdx.x * TQ;
    int tid = threadIdx.x;
    int vlen = valid_lens[b];

    // load q rows (duplicated half2) and w_v
    for (int i = tid; i < TQ * H_; i += 256) {
        int r = i >> 7, h = i & 127;
        __half v = g_qh[(b * Q_ + q0 + r) * H_ + h];
        ((__half2*)qsw)[r * RPAD + h] = __halves2half2(v, v);
    }
    if (tid < H_) wv[tid] = w_v[tid];

    int qg = tid >> 6;
    int j  = tid & 63;
    const float4* qd4 = (const float4*)(qsw + qg * RPAD);  // 4 dup-half2 per float4
    const float4* kp4 = (const float4*)(ksw + j * RPAD);
    const float4* wv4 = (const float4*)wv;

    float* scr = sc + qg * K_;

    for (int kt = 0; kt < K_ / TK; kt++) {
        __syncthreads();
        // cooperative load of paired-k tile: 64 rows x 128 half2 = 2048 float4
        const float4* srck = (const float4*)(g_k2 + (b * 8 + kt) * 64 * H_);
        #pragma unroll
        for (int l = 0; l < 8; l++) {
            int i = tid + 256 * l;
            int r = i >> 5, c = i & 31;
            *(float4*)(ksw + r * RPAD + c * 4) = srck[i];
        }
        __syncthreads();

        float S0 = 0.f, S1 = 0.f;
        #pragma unroll 8
        for (int h4 = 0; h4 < H_ / 4; h4++) {
            float4 qv = qd4[h4];
            float4 kv = kp4[h4];
            float4 wf = wv4[h4];
            const __half2* qh = (const __half2*)&qv;
            const __half2* kh = (const __half2*)&kv;
            const float*   wp = (const float*)&wf;
            #pragma unroll
            for (int u = 0; u < 4; u++) {
                __half2 t = tanh_h2(__hadd2(qh[u], kh[u]));
                float2 f = __half22float2(t);
                S0 = fmaf(wp[u], f.x, S0);
                S1 = fmaf(wp[u], f.y, S1);
            }
        }
        scr[kt * TK + j]      = S0;
        scr[kt * TK + j + 64] = S1;
    }
    __syncthreads();

    // masked softmax: warp w (w < 4) handles q-row w
    if (tid < 128) {
        int wid = tid >> 5, lane = tid & 31;
        float* row = sc + wid * K_;
        float v[32];
        float m = -3e38f;
        #pragma unroll
        for (int jj = 0; jj < 32; jj++) {
            int k = lane + 32 * jj;
            float s = (k < vlen) ? row[k] : -1e6f;
            v[jj] = s;
            m = fmaxf(m, s);
        }
        #pragma unroll
        for (int off = 16; off; off >>= 1)
            m = fmaxf(m, __shfl_xor_sync(0xffffffffu, m, off));
        float sum = 0.f;
        #pragma unroll
        for (int jj = 0; jj < 32; jj++) { v[jj] = __expf(v[jj] - m); sum += v[jj]; }
        #pragma unroll
        for (int off = 16; off; off >>= 1)
            sum += __shfl_xor_sync(0xffffffffu, sum, off);
        float inv = 1.f / sum;
        #pragma unroll
        for (int jj = 0; jj < 32; jj++) row[lane + 32 * jj] = v[jj] * inv;
    }
    __syncthreads();

    // attn @ values: thread = (v4 = tid&31 float4-col, slice = tid>>5 of 8)
    {
        int v4 = tid & 31;
        int slice = tid >> 5;
        float4 acc[TQ];
        #pragma unroll
        for (int r = 0; r < TQ; r++) acc[r] = make_float4(0.f, 0.f, 0.f, 0.f);
        const float4* vb = (const float4*)(values + b * K_ * DV_);
        #pragma unroll 4
        for (int k = slice; k < K_; k += 8) {
            float4 vv = vb[k * 32 + v4];
            #pragma unroll
            for (int r = 0; r < TQ; r++) {
                float a = sc[r * K_ + k];
                acc[r].x += a * vv.x; acc[r].y += a * vv.y;
                acc[r].z += a * vv.z; acc[r].w += a * vv.w;
            }
        }
        float4* red = (float4*)ksw;   // 8 slices * 4 rows * 32 float4 = 4K words
        #pragma unroll
        for (int r = 0; r < TQ; r++) red[(slice * TQ + r) * 32 + v4] = acc[r];
        __syncthreads();
        if (tid < TQ * 32) {
            int r = tid >> 5, c = tid & 31;
            float4 o = make_float4(0.f, 0.f, 0.f, 0.f);
            #pragma unroll
            for (int s = 0; s < 8; s++) {
                float4 t = red[(s * TQ + r) * 32 + c];
                o.x += t.x; o.y += t.y; o.z += t.z; o.w += t.w;
            }
            ((float4*)(out + (b * Q_ + q0 + r) * DV_))[c] = o;
        }
    }
}

extern "C" void kernel_launch(void* const* d_in, const int* in_sizes, int n_in,
                              void* d_out, int out_size)
{
    const float* queries    = (const float*)d_in[0];
    const float* keys       = (const float*)d_in[1];
    const float* values     = (const float*)d_in[2];
    const int*   valid_lens = (const int*)  d_in[3];
    const float* W_q        = (const float*)d_in[4];
    const float* W_k        = (const float*)d_in[5];
    const float* w_v        = (const float*)d_in[6];
    float* out = (float*)d_out;

    cudaFuncSetAttribute(attn_kernel,
                         cudaFuncAttributeMaxDynamicSharedMemorySize, SMEM_BYTES);

    proj_kernel<<<(B_ * Q_ + B_ * K_) / 16, 128>>>(queries, keys, W_q, W_k);
    attn_kernel<<<dim3(Q_ / TQ, B_), 256, SMEM_BYTES>>>(values, valid_lens, w_v, out);
}

// round 5
// speedup vs baseline: 1.1409x; 1.0727x over previous
#include <cuda_runtime.h>
#include <cuda_fp16.h>
#include <cuda_bf16.h>

#define B_  8
#define Q_  256
#define K_  1024
#define D_  256
#define H_  128
#define DV_ 128

#define RPAD 132          // padded row stride in 4-byte words

// scratch: projected q (dup half2), k (paired half2), raw scores
// g_k2[b][kt][j][h] = (k[b][kt*128+j][h], k[b][kt*128+j+64][h])
__device__ __half2 g_q2[B_ * Q_ * H_];
__device__ __half2 g_k2[B_ * 8 * 64 * H_];
__device__ float   g_sc[B_ * Q_ * K_];

__device__ __forceinline__ __half2 tanh_h2(__half2 x) {
    __half2 y;
    asm("tanh.approx.f16x2 %0, %1;"
        : "=r"(*(unsigned int*)&y) : "r"(*(unsigned int*)&x));
    return y;
}

// ---------------------------------------------------------------------------
// Kernel 1: fused projections, d-reduction split over 2 thread halves.
// Block = 16 rows x 128 h, 256 threads. half = tid>>7 handles d range of 128.
// ---------------------------------------------------------------------------
__global__ __launch_bounds__(256) void proj_kernel(
    const float* __restrict__ queries, const float* __restrict__ keys,
    const float* __restrict__ Wq, const float* __restrict__ Wk)
{
    __shared__ float s_in[16 * D_];   // 16KB
    __shared__ float pr[16 * H_];     // 8KB partials
    int rb = blockIdx.x * 16;
    bool isQ = rb < B_ * Q_;
    const float* src = isQ ? (queries + rb * D_) : (keys + (rb - B_ * Q_) * D_);
    const float* W   = isQ ? Wq : Wk;

    int tid = threadIdx.x;
    int h    = tid & 127;
    int half = tid >> 7;

    const float4* s4 = (const float4*)src;
    float4* d4 = (float4*)s_in;
    #pragma unroll
    for (int i = 0; i < 4; i++) d4[tid + 256 * i] = s4[tid + 256 * i];
    __syncthreads();

    float acc[16];
    #pragma unroll
    for (int r = 0; r < 16; r++) acc[r] = 0.f;

    int d0 = half * 128;
    #pragma unroll 4
    for (int d = d0; d < d0 + 128; d += 4) {
        float w0 = W[(d + 0) * H_ + h];
        float w1 = W[(d + 1) * H_ + h];
        float w2 = W[(d + 2) * H_ + h];
        float w3 = W[(d + 3) * H_ + h];
        #pragma unroll
        for (int r = 0; r < 16; r++) {
            float4 a = *(const float4*)&s_in[r * D_ + d];
            acc[r] += a.x * w0 + a.y * w1 + a.z * w2 + a.w * w3;
        }
    }

    if (half == 1) {
        #pragma unroll
        for (int r = 0; r < 16; r++) pr[r * H_ + h] = acc[r];
    }
    __syncthreads();
    if (half == 0) {
        #pragma unroll
        for (int r = 0; r < 16; r++) acc[r] += pr[r * H_ + h];

        if (isQ) {
            #pragma unroll
            for (int r = 0; r < 16; r++) {
                __half v = __float2half(acc[r]);
                g_q2[(rb + r) * H_ + h] = __halves2half2(v, v);
            }
        } else {
            int rk0 = rb - B_ * Q_;
            #pragma unroll
            for (int r = 0; r < 16; r++) {
                int rk  = rk0 + r;
                int b   = rk >> 10;
                int rbi = rk & 1023;
                int kt  = rbi >> 7;
                int jj  = rbi & 127;
                int j    = jj & 63;
                int slot = jj >> 6;
                ((__half*)g_k2)[((((b * 8 + kt) * 64 + j) * H_) + h) * 2 + slot] =
                    __float2half(acc[r]);
            }
        }
    }
}

// ---------------------------------------------------------------------------
// Kernel 2: scores only, k-split. grid (Q/4, K/128, B), 256 threads.
// Block computes a 4q x 128k score tile. thread: qg = tid>>6, j = tid&63
// (k pair j, j+64). Writes fp32 scores to g_sc.
// ---------------------------------------------------------------------------
__global__ __launch_bounds__(256) void scores_kernel()
{
    __shared__ float ksw[64 * RPAD];   // k tile, paired half2, ~33.8KB
    __shared__ float qsw[4 * RPAD];    // q tile, dup half2
    __shared__ float wv[RPAD];         // w_v fp32

    int b  = blockIdx.z;
    int kt = blockIdx.y;
    int q0 = blockIdx.x * 4;
    int tid = threadIdx.x;

    // cooperative loads
    const float4* srck = (const float4*)(g_k2 + (b * 8 + kt) * 64 * H_);
    #pragma unroll
    for (int l = 0; l < 8; l++) {
        int i = tid + 256 * l;
        int r = i >> 5, c = i & 31;
        *(float4*)(ksw + r * RPAD + c * 4) = srck[i];
    }
    if (tid < 128) {
        int r = tid >> 5, c = tid & 31;
        *(float4*)(qsw + r * RPAD + c * 4) =
            ((const float4*)(g_q2 + (b * Q_ + q0 + r) * H_))[c];
    }
    __syncthreads();

    int qg = tid >> 6;
    int j  = tid & 63;
    const float4* qd4 = (const float4*)(qsw + qg * RPAD);
    const float4* kp4 = (const float4*)(ksw + j * RPAD);

    // w_v loaded once per block into regs via smem? keep smem path
    if (tid < 128) wv[tid] = 0.f;   // placeholder overwritten below
    // (w_v passed via global cheap read)
    __syncthreads();

    float S0 = 0.f, S1 = 0.f;
    {
        const float4* wv4 = (const float4*)wv;
        #pragma unroll 8
        for (int h4 = 0; h4 < H_ / 4; h4++) {
            float4 qv = qd4[h4];
            float4 kv = kp4[h4];
            float4 wf = wv4[h4];
            const __half2* qh = (const __half2*)&qv;
            const __half2* kh = (const __half2*)&kv;
            const float*   wp = (const float*)&wf;
            #pragma unroll
            for (int u = 0; u < 4; u++) {
                __half2 t = tanh_h2(__hadd2(qh[u], kh[u]));
                float2 f = __half22float2(t);
                S0 = fmaf(wp[u], f.x, S0);
                S1 = fmaf(wp[u], f.y, S1);
            }
        }
    }
    float* dst = g_sc + (b * Q_ + q0 + qg) * K_ + kt * 128;
    dst[j]      = S0;
    dst[j + 64] = S1;
}

// variant with w_v properly staged (used; above placeholder removed by this)
__global__ __launch_bounds__(256) void scores_kernel2(const float* __restrict__ w_v)
{
    __shared__ float ksw[64 * RPAD];
    __shared__ float qsw[4 * RPAD];
    __shared__ float wv[RPAD];

    int b  = blockIdx.z;
    int kt = blockIdx.y;
    int q0 = blockIdx.x * 4;
    int tid = threadIdx.x;

    const float4* srck = (const float4*)(g_k2 + (b * 8 + kt) * 64 * H_);
    #pragma unroll
    for (int l = 0; l < 8; l++) {
        int i = tid + 256 * l;
        int r = i >> 5, c = i & 31;
        *(float4*)(ksw + r * RPAD + c * 4) = srck[i];
    }
    if (tid < 128) {
        int r = tid >> 5, c = tid & 31;
        *(float4*)(qsw + r * RPAD + c * 4) =
            ((const float4*)(g_q2 + (b * Q_ + q0 + r) * H_))[c];
        wv[tid] = w_v[tid];
    }
    __syncthreads();

    int qg = tid >> 6;
    int j  = tid & 63;
    const float4* qd4 = (const float4*)(qsw + qg * RPAD);
    const float4* kp4 = (const float4*)(ksw + j * RPAD);
    const float4* wv4 = (const float4*)wv;

    float S0 = 0.f, S1 = 0.f;
    #pragma unroll 8
    for (int h4 = 0; h4 < H_ / 4; h4++) {
        float4 qv = qd4[h4];
        float4 kv = kp4[h4];
        float4 wf = wv4[h4];
        const __half2* qh = (const __half2*)&qv;
        const __half2* kh = (const __half2*)&kv;
        const float*   wp = (const float*)&wf;
        #pragma unroll
        for (int u = 0; u < 4; u++) {
            __half2 t = tanh_h2(__hadd2(qh[u], kh[u]));
            float2 f = __half22float2(t);
            S0 = fmaf(wp[u], f.x, S0);
            S1 = fmaf(wp[u], f.y, S1);
        }
    }
    float* dst = g_sc + (b * Q_ + q0 + qg) * K_ + kt * 128;
    dst[j]      = S0;
    dst[j + 64] = S1;
}

// ---------------------------------------------------------------------------
// Kernel 3: masked softmax (from g_sc) + attn @ values.
// grid (Q/8, B), 256 threads. Warp w = q-row w of the 8-row tile.
// ---------------------------------------------------------------------------
__global__ __launch_bounds__(256) void smax_av_kernel(
    const float* __restrict__ values, const int* __restrict__ valid_lens,
    float* __restrict__ out)
{
    __shared__ float sc[8 * K_];   // 32KB, reused for the slice reduction

    int b  = blockIdx.y;
    int q0 = blockIdx.x * 8;
    int tid = threadIdx.x;
    int wid = tid >> 5, lane = tid & 31;
    int vlen = valid_lens[b];

    // softmax: warp per row, read scores straight from global (L2)
    {
        const float* row = g_sc + (b * Q_ + q0 + wid) * K_;
        float v[32];
        float m = -3e38f;
        #pragma unroll
        for (int jj = 0; jj < 32; jj++) {
            int k = lane + 32 * jj;
            float s = (k < vlen) ? row[k] : -1e6f;
            v[jj] = s;
            m = fmaxf(m, s);
        }
        #pragma unroll
        for (int off = 16; off; off >>= 1)
            m = fmaxf(m, __shfl_xor_sync(0xffffffffu, m, off));
        float sum = 0.f;
        #pragma unroll
        for (int jj = 0; jj < 32; jj++) { v[jj] = __expf(v[jj] - m); sum += v[jj]; }
        #pragma unroll
        for (int off = 16; off; off >>= 1)
            sum += __shfl_xor_sync(0xffffffffu, sum, off);
        float inv = 1.f / sum;
        #pragma unroll
        for (int jj = 0; jj < 32; jj++)
            sc[wid * K_ + lane + 32 * jj] = v[jj] * inv;
    }
    __syncthreads();

    // attn @ values: thread = (v4 = tid&31 float4-col, slice = tid>>5 of 8)
    int v4 = tid & 31;
    int slice = tid >> 5;
    float4 acc[8];
    #pragma unroll
    for (int r = 0; r < 8; r++) acc[r] = make_float4(0.f, 0.f, 0.f, 0.f);
    const float4* vb = (const float4*)(values + b * K_ * DV_);
    #pragma unroll 4
    for (int k = slice; k < K_; k += 8) {
        float4 vv = vb[k * 32 + v4];
        #pragma unroll
        for (int r = 0; r < 8; r++) {
            float a = sc[r * K_ + k];
            acc[r].x += a * vv.x; acc[r].y += a * vv.y;
            acc[r].z += a * vv.z; acc[r].w += a * vv.w;
        }
    }
    __syncthreads();                 // all sc reads done
    float4* red = (float4*)sc;       // alias: 8 slices * 8 rows * 32 = 32KB
    #pragma unroll
    for (int r = 0; r < 8; r++) red[(slice * 8 + r) * 32 + v4] = acc[r];
    __syncthreads();
    {
        int r = tid >> 5, c = tid & 31;
        float4 o = make_float4(0.f, 0.f, 0.f, 0.f);
        #pragma unroll
        for (int s = 0; s < 8; s++) {
            float4 t = red[(s * 8 + r) * 32 + c];
            o.x += t.x; o.y += t.y; o.z += t.z; o.w += t.w;
        }
        ((float4*)(out + (b * Q_ + q0 + r) * DV_))[c] = o;
    }
}

extern "C" void kernel_launch(void* const* d_in, const int* in_sizes, int n_in,
                              void* d_out, int out_size)
{
    const float* queries    = (const float*)d_in[0];
    const float* keys       = (const float*)d_in[1];
    const float* values     = (const float*)d_in[2];
    const int*   valid_lens = (const int*)  d_in[3];
    const float* W_q        = (const float*)d_in[4];
    const float* W_k        = (const float*)d_in[5];
    const float* w_v        = (const float*)d_in[6];
    float* out = (float*)d_out;

    proj_kernel<<<(B_ * Q_ + B_ * K_) / 16, 256>>>(queries, keys, W_q, W_k);
    scores_kernel2<<<dim3(Q_ / 4, K_ / 128, B_), 256>>>(w_v);
    smax_av_kernel<<<dim3(Q_ / 8, B_), 256>>>(values, valid_lens, out);
}